// round 10
// baseline (speedup 1.0000x reference)
#include <cuda_runtime.h>
#include <cstdint>

#define NODE_DIM 64
#define MSG_DIM  64
#define PROP_DIM 32
#define HIDDEN   128
#define T_DIM    8
#define S_DIM    16

#define MAX_V    10000

// Scratch: base[v][h] = h_t[v].Wh + theta[v].Wp + b1
__device__ float g_base[MAX_V * HIDDEN];

// pack two fp32 -> fp16x2 (lo = first arg), round-to-nearest-even
__device__ __forceinline__ uint32_t pack_h2(float lo, float hi) {
    uint32_t r;
    asm("cvt.rn.f16x2.f32 %0, %1, %2;" : "=r"(r) : "f"(hi), "f"(lo));
    return r;
}

#define MMA_F16(D, a0, a1, a2, a3, b0, b1)                                    \
    asm volatile(                                                             \
        "mma.sync.aligned.m16n8k16.row.col.f32.f16.f16.f32 "                  \
        "{%0,%1,%2,%3}, {%4,%5,%6,%7}, {%8,%9}, {%0,%1,%2,%3};"               \
        : "+f"(D[0]), "+f"(D[1]), "+f"(D[2]), "+f"(D[3])                      \
        : "r"(a0), "r"(a1), "r"(a2), "r"(a3), "r"(b0), "r"(b1))

// ---------------------------------------------------------------------------
// Kernel 1: base[v][h].  16 nodes per CTA, single pass.
// W1 rows: Wh = 0..63, Wm = 64..127, Wt = 128, Wp = 129..160
// ---------------------------------------------------------------------------
__global__ __launch_bounds__(256) void base_kernel(
    const float* __restrict__ h_t,
    const float* __restrict__ theta,
    const float* __restrict__ W1,
    const float* __restrict__ b1,
    int V)
{
    extern __shared__ float sm1[];
    float* Wsm  = sm1;               // 96*128
    float* b1sm = sm1 + 96 * 128;    // 128
    float* hsm  = b1sm + 128;        // 16*96

    const int tid = threadIdx.x;

    for (int i = tid; i < 96 * 128; i += 256) {
        int r = i >> 7;
        int c = i & 127;
        int gr = (r < NODE_DIM) ? r : (NODE_DIM + MSG_DIM + 1 + (r - NODE_DIM));
        Wsm[i] = W1[gr * HIDDEN + c];
    }
    if (tid < HIDDEN) b1sm[tid] = b1[tid];

    const int vp = blockIdx.x * 16;

    for (int i = tid; i < 16 * 64; i += 256) {
        int v = i >> 6, d = i & 63;
        hsm[v * 96 + d] = (vp + v < V) ? h_t[(size_t)(vp + v) * NODE_DIM + d] : 0.f;
    }
    for (int i = tid; i < 16 * 32; i += 256) {
        int v = i >> 5, p = i & 31;
        hsm[v * 96 + 64 + p] = (vp + v < V) ? theta[(size_t)(vp + v) * PROP_DIM + p] : 0.f;
    }
    __syncthreads();

    const int h4 = (tid & 31) * 4;
    const int vl = (tid >> 5) * 2;

    float4 acc0 = *(const float4*)&b1sm[h4];
    float4 acc1 = acc0;
    const float* hv0 = &hsm[vl * 96];
    const float* hv1 = hv0 + 96;

    #pragma unroll 8
    for (int d = 0; d < 96; ++d) {
        float4 ww = *(const float4*)&Wsm[d * 128 + h4];
        float x0 = hv0[d], x1 = hv1[d];
        acc0.x = fmaf(x0, ww.x, acc0.x);
        acc0.y = fmaf(x0, ww.y, acc0.y);
        acc0.z = fmaf(x0, ww.z, acc0.z);
        acc0.w = fmaf(x0, ww.w, acc0.w);
        acc1.x = fmaf(x1, ww.x, acc1.x);
        acc1.y = fmaf(x1, ww.y, acc1.y);
        acc1.z = fmaf(x1, ww.z, acc1.z);
        acc1.w = fmaf(x1, ww.w, acc1.w);
    }
    if (vp + vl < V)
        *(float4*)&g_base[(size_t)(vp + vl) * HIDDEN + h4] = acc0;
    if (vp + vl + 1 < V)
        *(float4*)&g_base[(size_t)(vp + vl + 1) * HIDDEN + h4] = acc1;
}

// ---------------------------------------------------------------------------
// Kernel 2: decoupled warp-pair fp16 mma, A fragments direct from global.
// No smem A tile, no CTA-wide sync in the loop: warps {2b,2b+1} cooperate
// only through a 64-thread named barrier, once per group, for the column
// reduce. Each pair owns a contiguous chunk of groups.
// ---------------------------------------------------------------------------

__global__ __launch_bounds__(128, 3) void main_kernel(
    const float* __restrict__ messages,
    const float* __restrict__ tau_values,
    const float* __restrict__ W1,
    const float* __restrict__ W2,
    const float* __restrict__ b2,
    float* __restrict__ out,
    int nGroups)
{
    __shared__ float taW[T_DIM][HIDDEN];     // tau_t * Wt[c]
    __shared__ float W2sm[HIDDEN];
    __shared__ float red[2][2][S_DIM][2];    // [pair][buf][row][half]

    const int tid   = threadIdx.x;
    const int lane  = tid & 31;
    const int w     = tid >> 5;
    const int qd    = lane & 3;        // thread-in-group
    const int gq    = lane >> 2;       // row within m16 tile
    const int chalf = w & 1;           // column half: cols [chalf*64, +64)
    const int pl    = w >> 1;          // pair index within CTA (0 or 1)
    const int wbase = chalf * 64;
    const int barid = 1 + pl;          // named barrier per pair

    // --- Persistent B fragments (fp16x2): 8 n-blocks of this warp's half ---
    uint32_t bf[8][4][2];
    {
        const float* Wm = W1 + NODE_DIM * HIDDEN;
        #pragma unroll
        for (int nb = 0; nb < 8; ++nb) {
            const int col = wbase + nb * 8 + gq;
            #pragma unroll
            for (int kk = 0; kk < 4; ++kk) {
                const int kb = kk * 16 + 2 * qd;
                bf[nb][kk][0] = pack_h2(Wm[(kb)     * HIDDEN + col],
                                        Wm[(kb + 1) * HIDDEN + col]);
                bf[nb][kk][1] = pack_h2(Wm[(kb + 8) * HIDDEN + col],
                                        Wm[(kb + 9) * HIDDEN + col]);
            }
        }
    }

    // --- Epilogue constants in smem ---
    {
        const float* Wt = W1 + (NODE_DIM + MSG_DIM) * HIDDEN;
        float wt = Wt[tid];
        #pragma unroll
        for (int t = 0; t < T_DIM; ++t)
            taW[t][tid] = __ldg(&tau_values[t]) * wt;
        W2sm[tid] = W2[tid];
    }
    const float b2v = __ldg(&b2[0]);
    __syncthreads();   // taW/W2sm ready; ONLY CTA-wide sync in the kernel

    // --- Contiguous chunk of groups for this pair ---
    const int nPairs = gridDim.x * 2;
    const int pairG  = blockIdx.x * 2 + pl;
    const int chunk  = (nGroups + nPairs - 1) / nPairs;
    const int gBeg   = pairG * chunk;
    int gEnd         = gBeg + chunk;
    if (gEnd > nGroups) gEnd = nGroups;

    int buf = 0;
    for (int g = gBeg; g < gEnd; ++g) {
        // --- A fragments straight from global (16 x LDG.64, MLP=16) ---
        // float2 index: g*512 + gq*32 + qd  (+kk*8 / +256 rows / +4 cols)
        const float2* mg = (const float2*)messages + ((size_t)g << 9) + gq * 32 + qd;
        float2 L[4][4];
        #pragma unroll
        for (int kk = 0; kk < 4; ++kk) {
            L[kk][0] = __ldg(mg + kk * 8);
            L[kk][1] = __ldg(mg + kk * 8 + 256);
            L[kk][2] = __ldg(mg + kk * 8 + 4);
            L[kk][3] = __ldg(mg + kk * 8 + 260);
        }

        float acc[8][4];
        #pragma unroll
        for (int nb = 0; nb < 8; ++nb)
            #pragma unroll
            for (int i = 0; i < 4; ++i) acc[nb][i] = 0.f;

        #pragma unroll
        for (int kk = 0; kk < 4; ++kk) {
            uint32_t a0 = pack_h2(L[kk][0].x, L[kk][0].y);
            uint32_t a1 = pack_h2(L[kk][1].x, L[kk][1].y);
            uint32_t a2 = pack_h2(L[kk][2].x, L[kk][2].y);
            uint32_t a3 = pack_h2(L[kk][3].x, L[kk][3].y);
            #pragma unroll
            for (int nb = 0; nb < 8; ++nb)
                MMA_F16(acc[nb], a0, a1, a2, a3, bf[nb][kk][0], bf[nb][kk][1]);
        }

        // --- Epilogue: +base +tau*Wt, relu, *W2; two FMA chains ---
        const float* bsrc = g_base + ((size_t)(g >> 3) << 7);
        const float* taWj = taW[g & (T_DIM - 1)];
        float pl0 = 0.f, pl1 = 0.f, ph0 = 0.f, ph1 = 0.f;
        #pragma unroll
        for (int nb = 0; nb < 8; ++nb) {
            const int c0 = wbase + nb * 8 + qd * 2;
            float2 bv = __ldg((const float2*)(bsrc + c0));
            float2 tw = *(const float2*)&taWj[c0];
            float2 w2 = *(const float2*)&W2sm[c0];
            float add0 = bv.x + tw.x;
            float add1 = bv.y + tw.y;
            if (nb & 1) {
                pl1 = fmaf(fmaxf(acc[nb][0] + add0, 0.f), w2.x, pl1);
                pl1 = fmaf(fmaxf(acc[nb][1] + add1, 0.f), w2.y, pl1);
                ph1 = fmaf(fmaxf(acc[nb][2] + add0, 0.f), w2.x, ph1);
                ph1 = fmaf(fmaxf(acc[nb][3] + add1, 0.f), w2.y, ph1);
            } else {
                pl0 = fmaf(fmaxf(acc[nb][0] + add0, 0.f), w2.x, pl0);
                pl0 = fmaf(fmaxf(acc[nb][1] + add1, 0.f), w2.y, pl0);
                ph0 = fmaf(fmaxf(acc[nb][2] + add0, 0.f), w2.x, ph0);
                ph0 = fmaf(fmaxf(acc[nb][3] + add1, 0.f), w2.y, ph0);
            }
        }
        float ps_lo = pl0 + pl1;
        float ps_hi = ph0 + ph1;
        ps_lo += __shfl_xor_sync(0xffffffffu, ps_lo, 1);
        ps_lo += __shfl_xor_sync(0xffffffffu, ps_lo, 2);
        ps_hi += __shfl_xor_sync(0xffffffffu, ps_hi, 1);
        ps_hi += __shfl_xor_sync(0xffffffffu, ps_hi, 2);
        if (qd == 0) {
            red[pl][buf][gq][chalf]     = ps_lo;
            red[pl][buf][gq + 8][chalf] = ps_hi;
        }

        // pairwise barrier: partner's red half visible
        asm volatile("bar.sync %0, 64;" :: "r"(barid) : "memory");

        if (chalf == 0 && lane < S_DIM) {
            out[(size_t)g * S_DIM + lane] =
                red[pl][buf][lane][0] + red[pl][buf][lane][1] + b2v;
        }
        // red double-buffered: next write targets buf^1; by the time buf is
        // written again (2 groups later) both warps have passed 2 barriers.
        buf ^= 1;
    }
}

// ---------------------------------------------------------------------------
extern "C" void kernel_launch(void* const* d_in, const int* in_sizes, int n_in,
                              void* d_out, int out_size)
{
    const float* h_t      = (const float*)d_in[0];
    const float* messages = (const float*)d_in[1];
    const float* tau      = (const float*)d_in[2];
    const float* theta    = (const float*)d_in[3];
    const float* W1       = (const float*)d_in[4];
    const float* b1       = (const float*)d_in[5];
    const float* W2       = (const float*)d_in[6];
    const float* b2       = (const float*)d_in[7];
    float* out = (float*)d_out;

    const int V = in_sizes[0] / NODE_DIM;
    const int nGroups = V * T_DIM;

    const int smem1 = (96 * 128 + 128 + 16 * 96) * (int)sizeof(float);
    cudaFuncSetAttribute(base_kernel,
                         cudaFuncAttributeMaxDynamicSharedMemorySize, smem1);
    base_kernel<<<(V + 15) / 16, 256, smem1>>>(h_t, theta, W1, b1, V);

    // Grid = resident CTA count (persistent pairs).
    int nb_occ = 0, nsm = 148;
    cudaOccupancyMaxActiveBlocksPerMultiprocessor(&nb_occ, main_kernel, 128, 0);
    cudaDeviceGetAttribute(&nsm, cudaDevAttrMultiProcessorCount, 0);
    if (nb_occ < 1) nb_occ = 3;
    int grid = nb_occ * nsm;
    const int maxPairsGrid = (nGroups + 1) / 2;
    if (grid > maxPairsGrid) grid = maxPairsGrid;

    main_kernel<<<grid, 128>>>(messages, tau, W1, W2, b2, out, nGroups);
}

// round 11
// speedup vs baseline: 1.4962x; 1.4962x over previous
#include <cuda_runtime.h>
#include <cstdint>

#define NODE_DIM 64
#define MSG_DIM  64
#define PROP_DIM 32
#define HIDDEN   128
#define T_DIM    8
#define S_DIM    16

#define MAX_V    10000
#define GQ 4             // groups per CTA iteration
#define FSTR 72          // fp32 floats per A row in smem: conflict-free LDS.64
#define GROUP_FLOATS (S_DIM * FSTR)   // 1152

// Scratch: base[v][h] = h_t[v].Wh + theta[v].Wp + b1
__device__ float g_base[MAX_V * HIDDEN];

// pack two fp32 -> fp16x2 (lo = first arg), round-to-nearest-even
__device__ __forceinline__ uint32_t pack_h2(float lo, float hi) {
    uint32_t r;
    asm("cvt.rn.f16x2.f32 %0, %1, %2;" : "=r"(r) : "f"(hi), "f"(lo));
    return r;
}

#define MMA_F16(D, a0, a1, a2, a3, b0, b1)                                    \
    asm volatile(                                                             \
        "mma.sync.aligned.m16n8k16.row.col.f32.f16.f16.f32 "                  \
        "{%0,%1,%2,%3}, {%4,%5,%6,%7}, {%8,%9}, {%0,%1,%2,%3};"               \
        : "+f"(D[0]), "+f"(D[1]), "+f"(D[2]), "+f"(D[3])                      \
        : "r"(a0), "r"(a1), "r"(a2), "r"(a3), "r"(b0), "r"(b1))

__device__ __forceinline__ void cp_async16(uint32_t dst_smem, const void* src) {
    asm volatile("cp.async.cg.shared.global [%0], [%1], 16;" :: "r"(dst_smem), "l"(src));
}

// ---------------------------------------------------------------------------
// Kernel 1 (lean): base[v][h] = b1 + h_t[v].Wh + theta[v].Wp
// W read directly from L2 (broadcast across CTAs); only h/theta staged.
// W1 rows: Wh = 0..63, Wm = 64..127, Wt = 128, Wp = 129..160
// row(d) = d + (d>>6)*65  maps d in [0,96) -> {0..63, 129..160}
// ---------------------------------------------------------------------------
__global__ __launch_bounds__(256) void base_kernel(
    const float* __restrict__ h_t,
    const float* __restrict__ theta,
    const float* __restrict__ W1,
    const float* __restrict__ b1,
    int V)
{
    __shared__ float hsm[16 * 96];   // [v][d<64]=h_t, [v][64+p]=theta

    const int tid = threadIdx.x;
    const int vp  = blockIdx.x * 16;

    for (int i = tid; i < 16 * 64; i += 256) {
        int v = i >> 6, d = i & 63;
        hsm[v * 96 + d] = (vp + v < V) ? h_t[(size_t)(vp + v) * NODE_DIM + d] : 0.f;
    }
    for (int i = tid; i < 16 * 32; i += 256) {
        int v = i >> 5, p = i & 31;
        hsm[v * 96 + 64 + p] = (vp + v < V) ? theta[(size_t)(vp + v) * PROP_DIM + p] : 0.f;
    }
    __syncthreads();

    const int h4 = (tid & 31) * 4;    // 4 consecutive hidden cols
    const int vl = (tid >> 5) * 2;    // 2 nodes per thread

    float4 acc0 = __ldg((const float4*)&b1[h4]);
    float4 acc1 = acc0;
    const float* hv0 = &hsm[vl * 96];
    const float* hv1 = hv0 + 96;

    #pragma unroll 8
    for (int d = 0; d < 96; ++d) {
        const int row = d + ((d >> 6) * 65);
        float4 ww = __ldg((const float4*)&W1[row * HIDDEN + h4]);
        float x0 = hv0[d], x1 = hv1[d];
        acc0.x = fmaf(x0, ww.x, acc0.x);
        acc0.y = fmaf(x0, ww.y, acc0.y);
        acc0.z = fmaf(x0, ww.z, acc0.z);
        acc0.w = fmaf(x0, ww.w, acc0.w);
        acc1.x = fmaf(x1, ww.x, acc1.x);
        acc1.y = fmaf(x1, ww.y, acc1.y);
        acc1.z = fmaf(x1, ww.z, acc1.z);
        acc1.w = fmaf(x1, ww.w, acc1.w);
    }
    if (vp + vl < V)
        *(float4*)&g_base[(size_t)(vp + vl) * HIDDEN + h4] = acc0;
    if (vp + vl + 1 < V)
        *(float4*)&g_base[(size_t)(vp + vl + 1) * HIDDEN + h4] = acc1;
}

// ---------------------------------------------------------------------------
// Kernel 2: single-sync cp.async pipeline, warp-pair fp16 mma, lean epilogue.
// (R9 structure — best measured: 78.9us)
// ---------------------------------------------------------------------------

__device__ __forceinline__ void stage_quad(
    float* Asb, float* bsb,
    const float* __restrict__ messages, int q, int tid)
{
    const float* msrc = messages + (size_t)q * (GQ * S_DIM * MSG_DIM);
    #pragma unroll
    for (int i = 0; i < 8; ++i) {
        int c   = tid + i * 128;      // 16B chunk index, 0..1023
        int grp = c >> 8;
        int m   = c & 255;
        int row = m >> 4;
        int cc  = m & 15;
        uint32_t dst = (uint32_t)__cvta_generic_to_shared(
            Asb + grp * GROUP_FLOATS + row * FSTR + cc * 4);
        cp_async16(dst, msrc + c * 4);
    }
    if (tid < 32) {
        int v = q >> 1;   // quad q -> node q/2
        uint32_t dst = (uint32_t)__cvta_generic_to_shared(bsb + tid * 4);
        cp_async16(dst, g_base + (size_t)v * HIDDEN + tid * 4);
    }
}

__global__ __launch_bounds__(128, 4) void main_kernel(
    const float* __restrict__ messages,
    const float* __restrict__ tau_values,
    const float* __restrict__ W1,
    const float* __restrict__ W2,
    const float* __restrict__ b2,
    float* __restrict__ out,
    int nGroups, int nQuads)
{
    __shared__ float As[2][GQ * GROUP_FLOATS];       // 36864 B
    __shared__ float bsm[2][HIDDEN];                 // 1024 B
    __shared__ float red[2][GQ][S_DIM][2];           // 1024 B
    __shared__ float taW[T_DIM][HIDDEN];             // 4096 B
    __shared__ float W2sm[HIDDEN];                   // 512 B
    __shared__ float addsm[GQ][HIDDEN];              // 2048 B: base + tau*Wt per j

    const int tid   = threadIdx.x;
    const int lane  = tid & 31;
    const int w     = tid >> 5;
    const int qd    = lane & 3;        // thread-in-group
    const int gq    = lane >> 2;       // row within m16 tile
    const int chalf = w & 1;           // column half: cols [chalf*64, +64)
    const int jband = w >> 1;          // groups jband, jband+2 of the quad
    const int wbase = chalf * 64;

    const int grid = gridDim.x;
    int q = blockIdx.x;   // grid clamped to nQuads

    // Kick the first stage immediately; overlaps all prologue setup.
    stage_quad(As[0], bsm[0], messages, q, tid);
    asm volatile("cp.async.commit_group;");

    // --- Persistent B fragments (fp16x2): 8 n-blocks of this warp's half ---
    uint32_t bf[8][4][2];
    {
        const float* Wm = W1 + NODE_DIM * HIDDEN;
        #pragma unroll
        for (int nb = 0; nb < 8; ++nb) {
            const int col = wbase + nb * 8 + gq;
            #pragma unroll
            for (int kk = 0; kk < 4; ++kk) {
                const int kb = kk * 16 + 2 * qd;
                bf[nb][kk][0] = pack_h2(Wm[(kb)     * HIDDEN + col],
                                        Wm[(kb + 1) * HIDDEN + col]);
                bf[nb][kk][1] = pack_h2(Wm[(kb + 8) * HIDDEN + col],
                                        Wm[(kb + 9) * HIDDEN + col]);
            }
        }
    }

    // --- Epilogue constants in smem ---
    {
        const float* Wt = W1 + (NODE_DIM + MSG_DIM) * HIDDEN;
        float wt = Wt[tid];
        #pragma unroll
        for (int t = 0; t < T_DIM; ++t)
            taW[t][tid] = __ldg(&tau_values[t]) * wt;
        W2sm[tid] = W2[tid];
    }
    const float b2v = __ldg(&b2[0]);

    asm volatile("cp.async.wait_group 0;");
    __syncthreads();   // buf0 + taW/W2sm visible

    int cur = 0;
    for (;;) {
        const bool hasNext = (q + grid < nQuads);

        // (1) stage q+1 into other buffer (async; in flight through MMA phase)
        if (hasNext) {
            stage_quad(As[cur ^ 1], bsm[cur ^ 1], messages, q + grid, tid);
            asm volatile("cp.async.commit_group;");
        }

        const int g0 = q * GQ;
        const int t0 = g0 & (T_DIM - 1);

        // (2) per-warp addsm: add[j][c] = base[c] + tau*Wt[c] for own cols
        {
            const int col = wbase + lane * 2;   // lane*2 in [0,62]
            float2 bv = *(const float2*)&bsm[cur][col];
            #pragma unroll
            for (int jj = 0; jj < 2; ++jj) {
                const int j = jband + 2 * jj;
                float2 tw = *(const float2*)&taW[t0 + j][col];
                float2 ad;
                ad.x = bv.x + tw.x;
                ad.y = bv.y + tw.y;
                *(float2*)&addsm[j][col] = ad;
            }
        }
        __syncwarp();   // addsm written/read by this warp only

        // (3) MMA + epilogue on buf[cur]
        #pragma unroll
        for (int jj = 0; jj < 2; ++jj) {
            const int j = jband + 2 * jj;
            const float* Ab = &As[cur][j * GROUP_FLOATS];

            float acc[8][4];
            #pragma unroll
            for (int nb = 0; nb < 8; ++nb)
                #pragma unroll
                for (int i = 0; i < 4; ++i) acc[nb][i] = 0.f;

            #pragma unroll
            for (int kk = 0; kk < 4; ++kk) {
                const float* Ak = Ab + kk * 16 + 2 * qd;
                float2 v0 = *(const float2*)&Ak[gq * FSTR];
                float2 v1 = *(const float2*)&Ak[(gq + 8) * FSTR];
                float2 v2 = *(const float2*)&Ak[gq * FSTR + 8];
                float2 v3 = *(const float2*)&Ak[(gq + 8) * FSTR + 8];
                uint32_t a0 = pack_h2(v0.x, v0.y);
                uint32_t a1 = pack_h2(v1.x, v1.y);
                uint32_t a2 = pack_h2(v2.x, v2.y);
                uint32_t a3 = pack_h2(v3.x, v3.y);
                #pragma unroll
                for (int nb = 0; nb < 8; ++nb)
                    MMA_F16(acc[nb], a0, a1, a2, a3, bf[nb][kk][0], bf[nb][kk][1]);
            }

            // Lean epilogue: add precomputed, relu, *W2; two FMA chains
            const float* adj = addsm[j];
            float pl0 = 0.f, pl1 = 0.f, ph0 = 0.f, ph1 = 0.f;
            #pragma unroll
            for (int nb = 0; nb < 8; ++nb) {
                const int c0 = wbase + nb * 8 + qd * 2;
                float2 ad = *(const float2*)&adj[c0];
                float2 w2 = *(const float2*)&W2sm[c0];
                if (nb & 1) {
                    pl1 = fmaf(fmaxf(acc[nb][0] + ad.x, 0.f), w2.x, pl1);
                    pl1 = fmaf(fmaxf(acc[nb][1] + ad.y, 0.f), w2.y, pl1);
                    ph1 = fmaf(fmaxf(acc[nb][2] + ad.x, 0.f), w2.x, ph1);
                    ph1 = fmaf(fmaxf(acc[nb][3] + ad.y, 0.f), w2.y, ph1);
                } else {
                    pl0 = fmaf(fmaxf(acc[nb][0] + ad.x, 0.f), w2.x, pl0);
                    pl0 = fmaf(fmaxf(acc[nb][1] + ad.y, 0.f), w2.y, pl0);
                    ph0 = fmaf(fmaxf(acc[nb][2] + ad.x, 0.f), w2.x, ph0);
                    ph0 = fmaf(fmaxf(acc[nb][3] + ad.y, 0.f), w2.y, ph0);
                }
            }
            float ps_lo = pl0 + pl1;
            float ps_hi = ph0 + ph1;
            ps_lo += __shfl_xor_sync(0xffffffffu, ps_lo, 1);
            ps_lo += __shfl_xor_sync(0xffffffffu, ps_lo, 2);
            ps_hi += __shfl_xor_sync(0xffffffffu, ps_hi, 1);
            ps_hi += __shfl_xor_sync(0xffffffffu, ps_hi, 2);
            if (qd == 0) {
                red[cur][j][gq][chalf]     = ps_lo;
                red[cur][j][gq + 8][chalf] = ps_hi;
            }
        }

        // (4) drain next-stage cp.async, single sync
        if (hasNext) asm volatile("cp.async.wait_group 0;");
        __syncthreads();   // buf[cur^1]+bsm staged AND red[cur] ready

        // (5) out-store quad q (red double-buffered)
        if (tid < GQ * S_DIM) {
            const int j   = tid >> 4;
            const int row = tid & 15;
            const int g   = g0 + j;
            if (g < nGroups)
                out[(size_t)g * S_DIM + row] =
                    red[cur][j][row][0] + red[cur][j][row][1] + b2v;
        }

        if (!hasNext) break;
        cur ^= 1;
        q += grid;
    }
}

// ---------------------------------------------------------------------------
extern "C" void kernel_launch(void* const* d_in, const int* in_sizes, int n_in,
                              void* d_out, int out_size)
{
    const float* h_t      = (const float*)d_in[0];
    const float* messages = (const float*)d_in[1];
    const float* tau      = (const float*)d_in[2];
    const float* theta    = (const float*)d_in[3];
    const float* W1       = (const float*)d_in[4];
    const float* b1       = (const float*)d_in[5];
    const float* W2       = (const float*)d_in[6];
    const float* b2       = (const float*)d_in[7];
    float* out = (float*)d_out;

    const int V = in_sizes[0] / NODE_DIM;
    const int nGroups = V * T_DIM;
    const int nQuads  = nGroups / GQ;

    base_kernel<<<(V + 15) / 16, 256>>>(h_t, theta, W1, b1, V);

    // Grid = resident CTA count (persistent style).
    int nb_occ = 0, nsm = 148;
    cudaOccupancyMaxActiveBlocksPerMultiprocessor(&nb_occ, main_kernel, 128, 0);
    cudaDeviceGetAttribute(&nsm, cudaDevAttrMultiProcessorCount, 0);
    if (nb_occ < 1) nb_occ = 4;
    int grid = nb_occ * nsm;
    if (grid > nQuads) grid = nQuads;

    main_kernel<<<grid, 128>>>(messages, tau, W1, W2, b2, out, nGroups, nQuads);
}

// round 12
// speedup vs baseline: 1.7784x; 1.1886x over previous
#include <cuda_runtime.h>
#include <cstdint>

#define NODE_DIM 64
#define MSG_DIM  64
#define PROP_DIM 32
#define HIDDEN   128
#define T_DIM    8
#define S_DIM    16

#define MAX_V    10000
#define GQ 4             // groups per CTA iteration (main)
#define FSTR 72          // fp32 floats per A row in smem: conflict-free LDS.64
#define GROUP_FLOATS (S_DIM * FSTR)   // 1152

// Scratch: base[v][h] = h_t[v].Wh + theta[v].Wp + b1
__device__ float g_base[MAX_V * HIDDEN];

// pack two fp32 -> fp16x2 (lo = first arg), round-to-nearest-even
__device__ __forceinline__ uint32_t pack_h2(float lo, float hi) {
    uint32_t r;
    asm("cvt.rn.f16x2.f32 %0, %1, %2;" : "=r"(r) : "f"(hi), "f"(lo));
    return r;
}

#define MMA_F16(D, a0, a1, a2, a3, b0, b1)                                    \
    asm volatile(                                                             \
        "mma.sync.aligned.m16n8k16.row.col.f32.f16.f16.f32 "                  \
        "{%0,%1,%2,%3}, {%4,%5,%6,%7}, {%8,%9}, {%0,%1,%2,%3};"               \
        : "+f"(D[0]), "+f"(D[1]), "+f"(D[2]), "+f"(D[3])                      \
        : "r"(a0), "r"(a1), "r"(a2), "r"(a3), "r"(b0), "r"(b1))

__device__ __forceinline__ void cp_async16(uint32_t dst_smem, const void* src) {
    asm volatile("cp.async.cg.shared.global [%0], [%1], 16;" :: "r"(dst_smem), "l"(src));
}

// ---------------------------------------------------------------------------
// Kernel 1 (tensorized): base[v][h] = b1 + [h_t|theta][v] @ W_sub
// W1 rows: Wh = 0..63, Wm = 64..127, Wt = 128, Wp = 129..160
// row(d) = d + (d>>6)*65 maps d in [0,96) -> {0..63, 129..160}
// One CTA = 32 nodes. Warp-pair layout identical to main kernel:
//   pl = warp>>1 picks node half (16 rows), chalf = warp&1 picks col half.
// A smem: fp16 [32 rows][stride 104 halfs] (u32 stride 52 -> conflict-free
// fragment LDS: banks (20*gq+qd) mod 32 all distinct).
// B smem: W_sub TRANSPOSED, fp16 [128 cols][stride 104 halfs], same stride.
// ---------------------------------------------------------------------------
__global__ __launch_bounds__(128) void base_mma_kernel(
    const float* __restrict__ h_t,
    const float* __restrict__ theta,
    const float* __restrict__ W1,
    const float* __restrict__ b1,
    int V)
{
    __shared__ uint32_t Asm[32 * 52];     // 6656 B
    __shared__ uint32_t Bts[128 * 52];    // 26624 B

    const int tid   = threadIdx.x;
    const int lane  = tid & 31;
    const int w     = tid >> 5;
    const int qd    = lane & 3;
    const int gq    = lane >> 2;
    const int chalf = w & 1;
    const int pl    = w >> 1;
    const int wbase = chalf * 64;
    const int v0    = blockIdx.x * 32;

    // --- Stage B transposed: thread owns col=tid, loops 48 k-pairs ---
    #pragma unroll 8
    for (int dp = 0; dp < 48; ++dp) {
        const int d0 = 2 * dp, d1 = 2 * dp + 1;
        const int r0 = d0 + ((d0 >> 6) * 65);
        const int r1 = d1 + ((d1 >> 6) * 65);
        float w0 = __ldg(&W1[r0 * HIDDEN + tid]);   // warp-coalesced 128B
        float w1 = __ldg(&W1[r1 * HIDDEN + tid]);
        Bts[tid * 52 + dp] = pack_h2(w0, w1);
    }

    // --- Stage A: rows = nodes, cols 0..63 = h_t, 64..95 = theta ---
    #pragma unroll
    for (int i = 0; i < 4; ++i) {
        const int c = tid + i * 128;          // 0..511
        const int n = c >> 4, f4 = c & 15;
        int v = v0 + n; if (v > V - 1) v = V - 1;
        float4 x = __ldg((const float4*)&h_t[(size_t)v * NODE_DIM + f4 * 4]);
        Asm[n * 52 + f4 * 2]     = pack_h2(x.x, x.y);
        Asm[n * 52 + f4 * 2 + 1] = pack_h2(x.z, x.w);
    }
    #pragma unroll
    for (int i = 0; i < 2; ++i) {
        const int c = tid + i * 128;          // 0..255
        const int n = c >> 3, f4 = c & 7;
        int v = v0 + n; if (v > V - 1) v = V - 1;
        float4 x = __ldg((const float4*)&theta[(size_t)v * PROP_DIM + f4 * 4]);
        Asm[n * 52 + 32 + f4 * 2]     = pack_h2(x.x, x.y);
        Asm[n * 52 + 32 + f4 * 2 + 1] = pack_h2(x.z, x.w);
    }
    __syncthreads();

    // --- MMA: 16x64 per warp, K=96 in 6 k-steps ---
    float acc[8][4];
    #pragma unroll
    for (int nb = 0; nb < 8; ++nb)
        #pragma unroll
        for (int i = 0; i < 4; ++i) acc[nb][i] = 0.f;

    const uint32_t* Arow = Asm + (pl * 16) * 52;
    #pragma unroll
    for (int kk = 0; kk < 6; ++kk) {
        const int ko = kk * 8 + qd;
        uint32_t a0 = Arow[gq * 52 + ko];
        uint32_t a1 = Arow[(gq + 8) * 52 + ko];
        uint32_t a2 = Arow[gq * 52 + ko + 4];
        uint32_t a3 = Arow[(gq + 8) * 52 + ko + 4];
        #pragma unroll
        for (int nb = 0; nb < 8; ++nb) {
            const uint32_t* Bc = Bts + (wbase + nb * 8 + gq) * 52 + ko;
            MMA_F16(acc[nb], a0, a1, a2, a3, Bc[0], Bc[4]);
        }
    }

    // --- Epilogue: +b1, guarded fp32 stores ---
    const int r_lo = v0 + pl * 16 + gq;
    const int r_hi = r_lo + 8;
    #pragma unroll
    for (int nb = 0; nb < 8; ++nb) {
        const int c0 = wbase + nb * 8 + qd * 2;
        float2 bv = __ldg((const float2*)&b1[c0]);
        if (r_lo < V) {
            float2 o; o.x = acc[nb][0] + bv.x; o.y = acc[nb][1] + bv.y;
            *(float2*)&g_base[(size_t)r_lo * HIDDEN + c0] = o;
        }
        if (r_hi < V) {
            float2 o; o.x = acc[nb][2] + bv.x; o.y = acc[nb][3] + bv.y;
            *(float2*)&g_base[(size_t)r_hi * HIDDEN + c0] = o;
        }
    }
}

// ---------------------------------------------------------------------------
// Kernel 2: single-sync cp.async pipeline, warp-pair fp16 mma, lean epilogue.
// (R9/R11 structure — best measured: 78.0us. UNCHANGED.)
// ---------------------------------------------------------------------------

__device__ __forceinline__ void stage_quad(
    float* Asb, float* bsb,
    const float* __restrict__ messages, int q, int tid)
{
    const float* msrc = messages + (size_t)q * (GQ * S_DIM * MSG_DIM);
    #pragma unroll
    for (int i = 0; i < 8; ++i) {
        int c   = tid + i * 128;      // 16B chunk index, 0..1023
        int grp = c >> 8;
        int m   = c & 255;
        int row = m >> 4;
        int cc  = m & 15;
        uint32_t dst = (uint32_t)__cvta_generic_to_shared(
            Asb + grp * GROUP_FLOATS + row * FSTR + cc * 4);
        cp_async16(dst, msrc + c * 4);
    }
    if (tid < 32) {
        int v = q >> 1;   // quad q -> node q/2
        uint32_t dst = (uint32_t)__cvta_generic_to_shared(bsb + tid * 4);
        cp_async16(dst, g_base + (size_t)v * HIDDEN + tid * 4);
    }
}

__global__ __launch_bounds__(128, 4) void main_kernel(
    const float* __restrict__ messages,
    const float* __restrict__ tau_values,
    const float* __restrict__ W1,
    const float* __restrict__ W2,
    const float* __restrict__ b2,
    float* __restrict__ out,
    int nGroups, int nQuads)
{
    __shared__ float As[2][GQ * GROUP_FLOATS];       // 36864 B
    __shared__ float bsm[2][HIDDEN];                 // 1024 B
    __shared__ float red[2][GQ][S_DIM][2];           // 1024 B
    __shared__ float taW[T_DIM][HIDDEN];             // 4096 B
    __shared__ float W2sm[HIDDEN];                   // 512 B
    __shared__ float addsm[GQ][HIDDEN];              // 2048 B

    const int tid   = threadIdx.x;
    const int lane  = tid & 31;
    const int w     = tid >> 5;
    const int qd    = lane & 3;
    const int gq    = lane >> 2;
    const int chalf = w & 1;
    const int jband = w >> 1;
    const int wbase = chalf * 64;

    const int grid = gridDim.x;
    int q = blockIdx.x;

    stage_quad(As[0], bsm[0], messages, q, tid);
    asm volatile("cp.async.commit_group;");

    uint32_t bf[8][4][2];
    {
        const float* Wm = W1 + NODE_DIM * HIDDEN;
        #pragma unroll
        for (int nb = 0; nb < 8; ++nb) {
            const int col = wbase + nb * 8 + gq;
            #pragma unroll
            for (int kk = 0; kk < 4; ++kk) {
                const int kb = kk * 16 + 2 * qd;
                bf[nb][kk][0] = pack_h2(Wm[(kb)     * HIDDEN + col],
                                        Wm[(kb + 1) * HIDDEN + col]);
                bf[nb][kk][1] = pack_h2(Wm[(kb + 8) * HIDDEN + col],
                                        Wm[(kb + 9) * HIDDEN + col]);
            }
        }
    }

    {
        const float* Wt = W1 + (NODE_DIM + MSG_DIM) * HIDDEN;
        float wt = Wt[tid];
        #pragma unroll
        for (int t = 0; t < T_DIM; ++t)
            taW[t][tid] = __ldg(&tau_values[t]) * wt;
        W2sm[tid] = W2[tid];
    }
    const float b2v = __ldg(&b2[0]);

    asm volatile("cp.async.wait_group 0;");
    __syncthreads();

    int cur = 0;
    for (;;) {
        const bool hasNext = (q + grid < nQuads);

        if (hasNext) {
            stage_quad(As[cur ^ 1], bsm[cur ^ 1], messages, q + grid, tid);
            asm volatile("cp.async.commit_group;");
        }

        const int g0 = q * GQ;
        const int t0 = g0 & (T_DIM - 1);

        {
            const int col = wbase + lane * 2;
            float2 bv = *(const float2*)&bsm[cur][col];
            #pragma unroll
            for (int jj = 0; jj < 2; ++jj) {
                const int j = jband + 2 * jj;
                float2 tw = *(const float2*)&taW[t0 + j][col];
                float2 ad;
                ad.x = bv.x + tw.x;
                ad.y = bv.y + tw.y;
                *(float2*)&addsm[j][col] = ad;
            }
        }
        __syncwarp();

        #pragma unroll
        for (int jj = 0; jj < 2; ++jj) {
            const int j = jband + 2 * jj;
            const float* Ab = &As[cur][j * GROUP_FLOATS];

            float acc[8][4];
            #pragma unroll
            for (int nb = 0; nb < 8; ++nb)
                #pragma unroll
                for (int i = 0; i < 4; ++i) acc[nb][i] = 0.f;

            #pragma unroll
            for (int kk = 0; kk < 4; ++kk) {
                const float* Ak = Ab + kk * 16 + 2 * qd;
                float2 v0 = *(const float2*)&Ak[gq * FSTR];
                float2 v1 = *(const float2*)&Ak[(gq + 8) * FSTR];
                float2 v2 = *(const float2*)&Ak[gq * FSTR + 8];
                float2 v3 = *(const float2*)&Ak[(gq + 8) * FSTR + 8];
                uint32_t a0 = pack_h2(v0.x, v0.y);
                uint32_t a1 = pack_h2(v1.x, v1.y);
                uint32_t a2 = pack_h2(v2.x, v2.y);
                uint32_t a3 = pack_h2(v3.x, v3.y);
                #pragma unroll
                for (int nb = 0; nb < 8; ++nb)
                    MMA_F16(acc[nb], a0, a1, a2, a3, bf[nb][kk][0], bf[nb][kk][1]);
            }

            const float* adj = addsm[j];
            float pl0 = 0.f, pl1 = 0.f, ph0 = 0.f, ph1 = 0.f;
            #pragma unroll
            for (int nb = 0; nb < 8; ++nb) {
                const int c0 = wbase + nb * 8 + qd * 2;
                float2 ad = *(const float2*)&adj[c0];
                float2 w2 = *(const float2*)&W2sm[c0];
                if (nb & 1) {
                    pl1 = fmaf(fmaxf(acc[nb][0] + ad.x, 0.f), w2.x, pl1);
                    pl1 = fmaf(fmaxf(acc[nb][1] + ad.y, 0.f), w2.y, pl1);
                    ph1 = fmaf(fmaxf(acc[nb][2] + ad.x, 0.f), w2.x, ph1);
                    ph1 = fmaf(fmaxf(acc[nb][3] + ad.y, 0.f), w2.y, ph1);
                } else {
                    pl0 = fmaf(fmaxf(acc[nb][0] + ad.x, 0.f), w2.x, pl0);
                    pl0 = fmaf(fmaxf(acc[nb][1] + ad.y, 0.f), w2.y, pl0);
                    ph0 = fmaf(fmaxf(acc[nb][2] + ad.x, 0.f), w2.x, ph0);
                    ph0 = fmaf(fmaxf(acc[nb][3] + ad.y, 0.f), w2.y, ph0);
                }
            }
            float ps_lo = pl0 + pl1;
            float ps_hi = ph0 + ph1;
            ps_lo += __shfl_xor_sync(0xffffffffu, ps_lo, 1);
            ps_lo += __shfl_xor_sync(0xffffffffu, ps_lo, 2);
            ps_hi += __shfl_xor_sync(0xffffffffu, ps_hi, 1);
            ps_hi += __shfl_xor_sync(0xffffffffu, ps_hi, 2);
            if (qd == 0) {
                red[cur][j][gq][chalf]     = ps_lo;
                red[cur][j][gq + 8][chalf] = ps_hi;
            }
        }

        if (hasNext) asm volatile("cp.async.wait_group 0;");
        __syncthreads();

        if (tid < GQ * S_DIM) {
            const int j   = tid >> 4;
            const int row = tid & 15;
            const int g   = g0 + j;
            if (g < nGroups)
                out[(size_t)g * S_DIM + row] =
                    red[cur][j][row][0] + red[cur][j][row][1] + b2v;
        }

        if (!hasNext) break;
        cur ^= 1;
        q += grid;
    }
}

// ---------------------------------------------------------------------------
extern "C" void kernel_launch(void* const* d_in, const int* in_sizes, int n_in,
                              void* d_out, int out_size)
{
    const float* h_t      = (const float*)d_in[0];
    const float* messages = (const float*)d_in[1];
    const float* tau      = (const float*)d_in[2];
    const float* theta    = (const float*)d_in[3];
    const float* W1       = (const float*)d_in[4];
    const float* b1       = (const float*)d_in[5];
    const float* W2       = (const float*)d_in[6];
    const float* b2       = (const float*)d_in[7];
    float* out = (float*)d_out;

    const int V = in_sizes[0] / NODE_DIM;
    const int nGroups = V * T_DIM;
    const int nQuads  = nGroups / GQ;

    base_mma_kernel<<<(V + 31) / 32, 128>>>(h_t, theta, W1, b1, V);

    // Grid = resident CTA count (persistent style).
    int nb_occ = 0, nsm = 148;
    cudaOccupancyMaxActiveBlocksPerMultiprocessor(&nb_occ, main_kernel, 128, 0);
    cudaDeviceGetAttribute(&nsm, cudaDevAttrMultiProcessorCount, 0);
    if (nb_occ < 1) nb_occ = 4;
    int grid = nb_occ * nsm;
    if (grid > nQuads) grid = nQuads;

    main_kernel<<<grid, 128>>>(messages, tau, W1, W2, b2, out, nGroups, nQuads);
}